// round 17
// baseline (speedup 1.0000x reference)
#include <cuda_runtime.h>
#include <cuda_bf16.h>

// ---------------- problem constants ----------------
#define QN    2500
#define NKK   10080
#define NKP   10112      // 158*64
#define HWIMG 1680
#define SCALE 0.17677669529663687f
#define NEGBIG 3.402823466e38f

#define BQ     64
#define TKK    64
#define NT_TOT 158
#define SPLITS 11
#define QT     40        // ceil(2500/64)
#define QPAD   (QT*BQ)   // 2560
#define THREADS 512

// smem word offsets (32-bit words). K rows 68w, Vt rows 36w, W/vis rows 68w, Ps rows 36w.
#define KBUF   (64*68)           // 4352
#define VBUF   (128*36)          // 4608
#define WBUF   (64*68)           // 4352
#define KOFF   0
#define VOFF   (2*KBUF)          // 8704
#define WOFF   (VOFF + 2*VBUF)   // 17920
#define VIOFF  (WOFF + 2*WBUF)   // 26624
#define PSOFF  (VIOFF + 2*WBUF)  // 35328
#define SMEMW  (PSOFF + 4*64*36) // 44544 words = 178176 B

// epilogue tiling
#define EPB    79                // ceil(2500/32)
#define EP_AS  129               // a/sk/zz row stride (floats)
#define EP_HS  257               // h row stride
#define EP_SMEMW (3*32*EP_AS + 32*EP_HS)   // 20608 words = 82432 B

// ---------------- scratch ----------------
__device__ __nv_bfloat16 g_qh [QPAD * 128];
__device__ __nv_bfloat16 g_kh [NKP  * 128];
__device__ __nv_bfloat16 g_vt [128  * NKP];     // transposed: [d][key]
__device__ float g_po [SPLITS * QPAD * 128];
__device__ float g_ps [SPLITS * QPAD * 4];

// ---------------- helpers ----------------
__device__ __forceinline__ void mma_bf16(float c[4], const unsigned a[4],
                                         unsigned b0, unsigned b1)
{
    asm volatile(
        "mma.sync.aligned.m16n8k16.row.col.f32.bf16.bf16.f32 "
        "{%0,%1,%2,%3}, {%4,%5,%6,%7}, {%8,%9}, {%0,%1,%2,%3};\n"
        : "+f"(c[0]), "+f"(c[1]), "+f"(c[2]), "+f"(c[3])
        : "r"(a[0]), "r"(a[1]), "r"(a[2]), "r"(a[3]), "r"(b0), "r"(b1));
}
__device__ __forceinline__ void cpa16(unsigned dst, const void* src, int nbytes)
{
    asm volatile("cp.async.cg.shared.global [%0], [%1], 16, %2;\n"
                 :: "r"(dst), "l"(src), "r"(nbytes));
}
#define CP_COMMIT() asm volatile("cp.async.commit_group;\n" ::: "memory")
#define CP_WAIT1()  asm volatile("cp.async.wait_group 1;\n" ::: "memory")

// =====================================================================
// Kernel 1: LayerNorm + 128x128 projection -> bf16 outputs.
//   mode 0: q src [D,2500], out row-major, scaled by SCALE
//   mode 1: k src [N,D,28,60], out row-major
//   mode 2: v src [N,D,28,60], out TRANSPOSED [d][NKP]
// =====================================================================
__global__ __launch_bounds__(256)
void ln_proj_kernel(const float* __restrict__ src,
                    const float* __restrict__ lnw, const float* __restrict__ lnb,
                    const float* __restrict__ Wm,  const float* __restrict__ bias,
                    __nv_bfloat16* __restrict__ out, int nrows, int mode)
{
    __shared__ float xs[32][129];
    const int tid  = threadIdx.x;
    const int row0 = blockIdx.x * 32;

    #pragma unroll
    for (int i = 0; i < 16; i++) {
        int idx = tid + 256 * i;
        int r = idx & 31, d = idx >> 5;
        int row = row0 + r;
        float v = 0.f;
        if (row < nrows) {
            int addr;
            if (mode == 0) addr = d * QN + row;
            else {
                int n  = row / HWIMG;
                int hw = row - n * HWIMG;
                addr = (n * 128 + d) * HWIMG + hw;
            }
            v = src[addr];
        }
        xs[r][d] = v;
    }
    __syncthreads();
    {
        int r = tid >> 3, sub = tid & 7;
        float s = 0.f, s2 = 0.f;
        #pragma unroll
        for (int kk = 0; kk < 16; kk++) {
            float x = xs[r][sub + 8 * kk];
            s += x; s2 += x * x;
        }
        #pragma unroll
        for (int o = 4; o; o >>= 1) {
            s  += __shfl_xor_sync(0xffffffffu, s,  o);
            s2 += __shfl_xor_sync(0xffffffffu, s2, o);
        }
        float mean = s * (1.f / 128.f);
        float var  = s2 * (1.f / 128.f) - mean * mean;
        float rs   = rsqrtf(var + 1e-5f);
        #pragma unroll
        for (int kk = 0; kk < 16; kk++) {
            int d = sub + 8 * kk;
            xs[r][d] = (xs[r][d] - mean) * rs * lnw[d] + lnb[d];
        }
    }
    __syncthreads();

    const int j  = tid & 127;
    const int rb = tid >> 7;
    float acc[16];
    float bj = bias[j];
    #pragma unroll
    for (int i = 0; i < 16; i++) acc[i] = bj;
    for (int d = 0; d < 128; d++) {
        float wv = Wm[d * 128 + j];
        #pragma unroll
        for (int i = 0; i < 16; i++)
            acc[i] = fmaf(xs[rb * 16 + i][d], wv, acc[i]);
    }
    const float mul = (mode == 0) ? SCALE : 1.f;
    #pragma unroll
    for (int i = 0; i < 16; i++) {
        int row = row0 + rb * 16 + i;
        if (row < nrows) {
            __nv_bfloat16 bv = __float2bfloat16(acc[i] * mul);
            if (mode == 2) out[(size_t)j * NKP + row] = bv;
            else           out[row * 128 + j] = bv;
        }
    }
}

// =====================================================================
// Kernel 2: bf16 tensor-core attention, cp.async double-buffered pipeline.
// (unchanged from R16 — verified at 126.6us)
// =====================================================================
__global__ __launch_bounds__(THREADS, 1)
void attn4_kernel(const float* __restrict__ Wl, const int* __restrict__ vis)
{
    extern __shared__ float sm[];
    const unsigned smem_b = (unsigned)__cvta_generic_to_shared(sm);

    const int tid  = threadIdx.x;
    const int lane = tid & 31, w = tid >> 5;
    const int h    = w & 3;                  // head
    const int mq   = w >> 2;                 // m-chunk (16 rows)
    const int g    = lane >> 2;              // 0..7
    const int tig  = lane & 3;               // 0..3

    const int sp = blockIdx.x / QT;
    const int qt = blockIdx.x % QT;
    const int q0 = qt * BQ;
    const int t0 = (NT_TOT * sp) / SPLITS;
    const int t1 = (NT_TOT * (sp + 1)) / SPLITS;

    // ---- Q A-fragments in registers (pre-scaled by SCALE in ln_proj) ----
    unsigned aQ[2][4];
    {
        const unsigned* qpu = (const unsigned*)g_qh
                            + (q0 + mq * 16 + g) * 64 + h * 16 + tig;
        #pragma unroll
        for (int ks = 0; ks < 2; ks++) {
            aQ[ks][0] = qpu[ks * 8];
            aQ[ks][1] = qpu[512 + ks * 8];
            aQ[ks][2] = qpu[ks * 8 + 4];
            aQ[ks][3] = qpu[512 + ks * 8 + 4];
        }
    }

    float o[4][4];
    #pragma unroll
    for (int nt = 0; nt < 4; nt++)
        #pragma unroll
        for (int e = 0; e < 4; e++) o[nt][e] = 0.f;
    float ssum0 = 0.f, ssum1 = 0.f;

    auto stage_tile = [&](int t, int b) {
        const int jb = t * TKK;
        #pragma unroll
        for (int i = 0; i < 2; i++) {
            int c = tid + THREADS * i;
            int row = c >> 4, cw = c & 15;
            unsigned dst = smem_b + (KOFF + b * KBUF) * 4 + row * 272 + cw * 16;
            const char* src = (const char*)g_kh + ((size_t)(jb + row) * 128 + cw * 8) * 2;
            cpa16(dst, src, 16);
        }
        #pragma unroll
        for (int i = 0; i < 2; i++) {
            int c = tid + THREADS * i;
            int d = c >> 3, jw = c & 7;
            unsigned dst = smem_b + (VOFF + b * VBUF) * 4 + d * 144 + jw * 16;
            const char* src = (const char*)g_vt + ((size_t)d * NKP + jb + jw * 8) * 2;
            cpa16(dst, src, 16);
        }
        #pragma unroll
        for (int i = 0; i < 2; i++) {
            int c = tid + THREADS * i;
            int qr = c >> 4, cw = c & 15;
            int qrow = q0 + qr;
            int col0 = jb + cw * 4;
            int nb = 0;
            if (qrow < QN) {
                nb = (NKK - col0) * 4;
                nb = nb < 0 ? 0 : (nb > 16 ? 16 : nb);
            }
            size_t off = (size_t)qrow * NKK + col0;
            const float* sw = (nb > 0) ? (Wl + off) : Wl;
            const int*   sv = (nb > 0) ? (vis + off) : vis;
            cpa16(smem_b + (WOFF  + b * WBUF) * 4 + qr * 272 + cw * 16, sw, nb);
            cpa16(smem_b + (VIOFF + b * WBUF) * 4 + qr * 272 + cw * 16, sv, nb);
        }
    };

    stage_tile(t0, 0);
    CP_COMMIT();
    if (t0 + 1 < t1) stage_tile(t0 + 1, 1);
    CP_COMMIT();

    unsigned* Psu = (unsigned*)(sm + PSOFF);
    const int r0 = mq * 16 + g;

    for (int t = t0; t < t1; t++) {
        const int b  = (t - t0) & 1;
        const int jb = t * TKK;
        CP_WAIT1();
        __syncthreads();

        const unsigned* Ku = (const unsigned*)(sm + KOFF + b * KBUF);
        const unsigned* Vu = (const unsigned*)(sm + VOFF + b * VBUF);
        const float*    Wb = sm + WOFF + b * WBUF;
        const int*      Vb = (const int*)(sm + VIOFF + b * WBUF);

        float c[8][4];
        #pragma unroll
        for (int nt = 0; nt < 8; nt++)
            #pragma unroll
            for (int e = 0; e < 4; e++) c[nt][e] = 0.f;

        #pragma unroll
        for (int ks = 0; ks < 2; ks++) {
            #pragma unroll
            for (int nt = 0; nt < 8; nt++) {
                const unsigned* kp = Ku + (nt * 8 + g) * 68 + h * 16 + ks * 8 + tig;
                mma_bf16(c[nt], aQ[ks], kp[0], kp[4]);
            }
        }

        {
            const int limit = NKK - jb;
            const int r0w = r0 * 68, r1w = r0w + 8 * 68;
            #pragma unroll
            for (int nt = 0; nt < 8; nt++) {
                const int kc = nt * 8 + 2 * tig;
                float2 w0 = *(const float2*)(Wb + r0w + kc);
                float2 w1 = *(const float2*)(Wb + r1w + kc);
                int2   v0 = *(const int2*)(Vb + r0w + kc);
                int2   v1 = *(const int2*)(Vb + r1w + kc);
                float p00 = __expf(w0.x * (v0.x ? c[nt][0] : -NEGBIG));
                float p01 = __expf(w0.y * (v0.y ? c[nt][1] : -NEGBIG));
                float p10 = __expf(w1.x * (v1.x ? c[nt][2] : -NEGBIG));
                float p11 = __expf(w1.y * (v1.y ? c[nt][3] : -NEGBIG));
                if (kc     >= limit) { p00 = 0.f; p10 = 0.f; }
                if (kc + 1 >= limit) { p01 = 0.f; p11 = 0.f; }
                ssum0 += p00 + p01;
                ssum1 += p10 + p11;
                unsigned P0, P1;
                asm("cvt.rn.bf16x2.f32 %0, %1, %2;" : "=r"(P0) : "f"(p01), "f"(p00));
                asm("cvt.rn.bf16x2.f32 %0, %1, %2;" : "=r"(P1) : "f"(p11), "f"(p10));
                Psu[(h * 64 + r0) * 36 + nt * 4 + tig]     = P0;
                Psu[(h * 64 + r0 + 8) * 36 + nt * 4 + tig] = P1;
            }
        }
        __syncwarp();

        unsigned pa[4][4];
        {
            const unsigned* pp0 = Psu + (h * 64 + r0) * 36 + tig;
            #pragma unroll
            for (int ks = 0; ks < 4; ks++) {
                pa[ks][0] = pp0[ks * 8];
                pa[ks][1] = pp0[288 + ks * 8];
                pa[ks][2] = pp0[ks * 8 + 4];
                pa[ks][3] = pp0[288 + ks * 8 + 4];
            }
        }
        #pragma unroll
        for (int ks = 0; ks < 4; ks++) {
            #pragma unroll
            for (int nt = 0; nt < 4; nt++) {
                const unsigned* vp = Vu + (h * 32 + nt * 8 + g) * 36 + ks * 8 + tig;
                mma_bf16(o[nt], pa[ks], vp[0], vp[4]);
            }
        }
        __syncthreads();

        if (t + 2 < t1) stage_tile(t + 2, b);
        CP_COMMIT();
    }

    ssum0 += __shfl_xor_sync(0xffffffffu, ssum0, 1);
    ssum0 += __shfl_xor_sync(0xffffffffu, ssum0, 2);
    ssum1 += __shfl_xor_sync(0xffffffffu, ssum1, 1);
    ssum1 += __shfl_xor_sync(0xffffffffu, ssum1, 2);
    const int qr = q0 + r0;
    if (tig == 0) {
        g_ps[((size_t)sp * QPAD + qr) * 4 + h]     = ssum0;
        g_ps[((size_t)sp * QPAD + qr + 8) * 4 + h] = ssum1;
    }
    #pragma unroll
    for (int nt = 0; nt < 4; nt++) {
        const int col = h * 32 + nt * 8 + 2 * tig;
        *(float2*)(g_po + ((size_t)sp * QPAD + qr) * 128 + col)     = make_float2(o[nt][0], o[nt][1]);
        *(float2*)(g_po + ((size_t)sp * QPAD + qr + 8) * 128 + col) = make_float2(o[nt][2], o[nt][3]);
    }
}

// =====================================================================
// Kernel 3 (NEW): batched epilogue, 32 rows/block, ln_proj-style GEMMs.
// combine partials -> proj+skip -> preLN -> MLP1+GELU -> MLP2+res -> postLN -> out.
// =====================================================================
__global__ __launch_bounds__(256)
void epilogue2_kernel(const float* __restrict__ wp,   const float* __restrict__ bp,
                      const float* __restrict__ skip,
                      const float* __restrict__ prew, const float* __restrict__ preb,
                      const float* __restrict__ w1,   const float* __restrict__ b1,
                      const float* __restrict__ w2,   const float* __restrict__ b2,
                      const float* __restrict__ postw,const float* __restrict__ postb,
                      float* __restrict__ out)
{
    extern __shared__ float esm[];
    float* a  = esm;                 // [32][EP_AS] attn-combined; later y
    float* sk = a  + 32 * EP_AS;     // [32][EP_AS] skip tile
    float* zz = sk + 32 * EP_AS;     // [32][EP_AS] pre-LN'd z
    float* hh = zz + 32 * EP_AS;     // [32][EP_HS] GELU hidden

    const int tid  = threadIdx.x;
    const int row0 = blockIdx.x * 32;

    // ---- phase 1: combine key-split partials + load skip tile ----
    #pragma unroll
    for (int i = 0; i < 16; i++) {
        int idx = tid + 256 * i;
        {   // combine: idx = r*128 + j (coalesced over g_po rows)
            int r = idx >> 7, j = idx & 127;
            int row = row0 + r;
            float av = 0.f;
            if (row < QN) {
                float dn = 0.f;
                #pragma unroll
                for (int s = 0; s < SPLITS; s++) {
                    size_t base = (size_t)s * QPAD + row;
                    av += g_po[base * 128 + j];
                    dn += g_ps[base * 4 + (j >> 5)];
                }
                av /= dn;
            }
            a[r * EP_AS + j] = av;
        }
        {   // skip: idx = d*32 + r (coalesced over skip rows)
            int d = idx >> 5, r = idx & 31;
            int row = row0 + r;
            sk[r * EP_AS + d] = (row < QN) ? skip[d * QN + row] : 0.f;
        }
    }
    __syncthreads();

    const int j  = tid & 127;
    const int rb = tid >> 7;

    // ---- GEMM1: z = a @ wp + bp + skip ----
    {
        float acc[16];
        #pragma unroll
        for (int i = 0; i < 16; i++) acc[i] = 0.f;
        for (int d = 0; d < 128; d++) {
            float wv = wp[d * 128 + j];
            #pragma unroll
            for (int i = 0; i < 16; i++)
                acc[i] = fmaf(a[(rb * 16 + i) * EP_AS + d], wv, acc[i]);
        }
        float bj = bp[j];
        #pragma unroll
        for (int i = 0; i < 16; i++) {
            int r = rb * 16 + i;
            zz[r * EP_AS + j] = acc[i] + bj + sk[r * EP_AS + j];
        }
    }
    __syncthreads();

    // ---- pre-LN (8 threads/row) ----
    {
        int r = tid >> 3, sub = tid & 7;
        float s = 0.f, s2 = 0.f;
        #pragma unroll
        for (int kk = 0; kk < 16; kk++) {
            float x = zz[r * EP_AS + sub + 8 * kk];
            s += x; s2 += x * x;
        }
        #pragma unroll
        for (int o = 4; o; o >>= 1) {
            s  += __shfl_xor_sync(0xffffffffu, s,  o);
            s2 += __shfl_xor_sync(0xffffffffu, s2, o);
        }
        float mean = s * (1.f / 128.f);
        float var  = s2 * (1.f / 128.f) - mean * mean;
        float rs   = rsqrtf(var + 1e-5f);
        #pragma unroll
        for (int kk = 0; kk < 16; kk++) {
            int d = sub + 8 * kk;
            zz[r * EP_AS + d] = (zz[r * EP_AS + d] - mean) * rs * prew[d] + preb[d];
        }
    }
    __syncthreads();

    // ---- GEMM2: h = GELU(z @ w1 + b1), 256 cols (2 per thread) ----
    #pragma unroll
    for (int cc = 0; cc < 2; cc++) {
        int c = j + 128 * cc;
        float acc[16];
        #pragma unroll
        for (int i = 0; i < 16; i++) acc[i] = 0.f;
        for (int d = 0; d < 128; d++) {
            float wv = w1[d * 256 + c];
            #pragma unroll
            for (int i = 0; i < 16; i++)
                acc[i] = fmaf(zz[(rb * 16 + i) * EP_AS + d], wv, acc[i]);
        }
        float bj = b1[c];
        #pragma unroll
        for (int i = 0; i < 16; i++) {
            float hv = acc[i] + bj;
            hh[(rb * 16 + i) * EP_HS + c] =
                0.5f * hv * (1.0f + erff(hv * 0.70710678118654752f));
        }
    }
    __syncthreads();

    // ---- GEMM3: y = h @ w2 + b2 + z ----
    {
        float acc[16];
        #pragma unroll
        for (int i = 0; i < 16; i++) acc[i] = 0.f;
        for (int c = 0; c < 256; c++) {
            float wv = w2[c * 128 + j];
            #pragma unroll
            for (int i = 0; i < 16; i++)
                acc[i] = fmaf(hh[(rb * 16 + i) * EP_HS + c], wv, acc[i]);
        }
        float bj = b2[j];
        #pragma unroll
        for (int i = 0; i < 16; i++) {
            int r = rb * 16 + i;
            a[r * EP_AS + j] = acc[i] + bj + zz[r * EP_AS + j];
        }
    }
    __syncthreads();

    // ---- post-LN (8 threads/row) ----
    {
        int r = tid >> 3, sub = tid & 7;
        float s = 0.f, s2 = 0.f;
        #pragma unroll
        for (int kk = 0; kk < 16; kk++) {
            float x = a[r * EP_AS + sub + 8 * kk];
            s += x; s2 += x * x;
        }
        #pragma unroll
        for (int o = 4; o; o >>= 1) {
            s  += __shfl_xor_sync(0xffffffffu, s,  o);
            s2 += __shfl_xor_sync(0xffffffffu, s2, o);
        }
        float mean = s * (1.f / 128.f);
        float var  = s2 * (1.f / 128.f) - mean * mean;
        float rs   = rsqrtf(var + 1e-5f);
        #pragma unroll
        for (int kk = 0; kk < 16; kk++) {
            int d = sub + 8 * kk;
            a[r * EP_AS + d] = (a[r * EP_AS + d] - mean) * rs * postw[d] + postb[d];
        }
    }
    __syncthreads();

    // ---- transposed store: out[d][row] ----
    #pragma unroll
    for (int i = 0; i < 16; i++) {
        int idx = tid + 256 * i;
        int d = idx >> 5, r = idx & 31;
        int row = row0 + r;
        if (row < QN) out[d * QN + row] = a[r * EP_AS + d];
    }
}

// =====================================================================
extern "C" void kernel_launch(void* const* d_in, const int* in_sizes, int n_in,
                              void* d_out, int out_size)
{
    const float* q      = (const float*)d_in[0];
    const float* k      = (const float*)d_in[1];
    const float* v      = (const float*)d_in[2];
    const float* Wl     = (const float*)d_in[3];
    const int*   vis    = (const int*)  d_in[4];
    const float* skip   = (const float*)d_in[5];
    const float* qn_w   = (const float*)d_in[6];
    const float* qn_b   = (const float*)d_in[7];
    const float* kn_w   = (const float*)d_in[8];
    const float* kn_b   = (const float*)d_in[9];
    const float* vn_w   = (const float*)d_in[10];
    const float* vn_b   = (const float*)d_in[11];
    const float* pre_w  = (const float*)d_in[12];
    const float* pre_b  = (const float*)d_in[13];
    const float* post_w = (const float*)d_in[14];
    const float* post_b = (const float*)d_in[15];
    const float* wq     = (const float*)d_in[16];
    const float* bq     = (const float*)d_in[17];
    const float* wk     = (const float*)d_in[18];
    const float* bk     = (const float*)d_in[19];
    const float* wv     = (const float*)d_in[20];
    const float* bv     = (const float*)d_in[21];
    const float* wp     = (const float*)d_in[22];
    const float* bp     = (const float*)d_in[23];
    const float* w1     = (const float*)d_in[24];
    const float* b1     = (const float*)d_in[25];
    const float* w2     = (const float*)d_in[26];
    const float* b2     = (const float*)d_in[27];
    float* out = (float*)d_out;

    __nv_bfloat16 *qh, *kh, *vt;
    cudaGetSymbolAddress((void**)&qh, g_qh);
    cudaGetSymbolAddress((void**)&kh, g_kh);
    cudaGetSymbolAddress((void**)&vt, g_vt);

    cudaFuncSetAttribute(attn4_kernel,
                         cudaFuncAttributeMaxDynamicSharedMemorySize,
                         SMEMW * 4);
    cudaFuncSetAttribute(epilogue2_kernel,
                         cudaFuncAttributeMaxDynamicSharedMemorySize,
                         EP_SMEMW * 4);

    ln_proj_kernel<<<(QN + 31) / 32, 256>>>(q, qn_w, qn_b, wq, bq, qh, QN, 0);
    ln_proj_kernel<<<NKK / 32, 256>>>(k, kn_w, kn_b, wk, bk, kh, NKK, 1);
    ln_proj_kernel<<<NKK / 32, 256>>>(v, vn_w, vn_b, wv, bv, vt, NKK, 2);

    attn4_kernel<<<SPLITS * QT, THREADS, SMEMW * 4>>>(Wl, vis);

    epilogue2_kernel<<<EPB, 256, EP_SMEMW * 4>>>(wp, bp, skip, pre_w, pre_b,
                                                 w1, b1, w2, b2, post_w, post_b, out);
}